// round 1
// baseline (speedup 1.0000x reference)
#include <cuda_runtime.h>
#include <math.h>

#define NB    2
#define NL    2048
#define NDIN  1024
#define NDOUT 1024
#define NH    16
#define NHD   64
#define NBH   (NB * NH)

// Scratch (static __device__ globals: allocation-free per harness rules)
__device__ float g_q[NBH * NL * NHD];              // [b,h,l,d] 16 MB
__device__ float g_k[NBH * NL * NHD];
__device__ float g_v[NBH * NL * NHD];
__device__ float g_ctx[NB * NL * NDOUT];           // [b,l,h*hd] 16 MB
__device__ float g_qr[(size_t)NBH * NL * NL];      // [bh,i,k] 536 MB (causal band written)

// ---------------------------------------------------------------------------
// SGEMM 128x128x8, 256 threads, 8x8 register tile.
// A row-major [M,K], B row-major [K,N].
// ---------------------------------------------------------------------------

__global__ void __launch_bounds__(256, 2) gemm_qkv(
    const float* __restrict__ x, const float* __restrict__ Wq,
    const float* __restrict__ Wk, const float* __restrict__ Wv)
{
    __shared__ float As[8][128];
    __shared__ float Bs[8][128];
    const float* W;
    float* outp;
    if (blockIdx.z == 0)      { W = Wq; outp = g_q; }
    else if (blockIdx.z == 1) { W = Wk; outp = g_k; }
    else                      { W = Wv; outp = g_v; }
    const int m0 = blockIdx.y * 128;
    const int n0 = blockIdx.x * 128;
    const int tid  = threadIdx.x;
    const int trow = tid >> 4, tcol = tid & 15;
    const int arow = tid >> 1, acol = (tid & 1) * 4;
    const int brow = tid >> 5, bcol = (tid & 31) * 4;
    float acc[8][8] = {};
    for (int k0 = 0; k0 < NDIN; k0 += 8) {
        float4 av = *(const float4*)&x[(size_t)(m0 + arow) * NDIN + k0 + acol];
        float4 bv = *(const float4*)&W[(size_t)(k0 + brow) * NDOUT + n0 + bcol];
        __syncthreads();
        As[acol + 0][arow] = av.x;
        As[acol + 1][arow] = av.y;
        As[acol + 2][arow] = av.z;
        As[acol + 3][arow] = av.w;
        *(float4*)&Bs[brow][bcol] = bv;
        __syncthreads();
#pragma unroll
        for (int k = 0; k < 8; k++) {
            float a[8], b[8];
            *(float4*)&a[0] = *(const float4*)&As[k][trow * 8];
            *(float4*)&a[4] = *(const float4*)&As[k][trow * 8 + 4];
            *(float4*)&b[0] = *(const float4*)&Bs[k][tcol * 8];
            *(float4*)&b[4] = *(const float4*)&Bs[k][tcol * 8 + 4];
#pragma unroll
            for (int i = 0; i < 8; i++)
#pragma unroll
                for (int j = 0; j < 8; j++)
                    acc[i][j] = fmaf(a[i], b[j], acc[i][j]);
        }
    }
#pragma unroll
    for (int i = 0; i < 8; i++) {
        int m  = m0 + trow * 8 + i;
        int bb = m >> 11;          // / NL
        int l  = m & (NL - 1);
#pragma unroll
        for (int j = 0; j < 8; j++) {
            int c = n0 + tcol * 8 + j;
            int h = c >> 6;
            int d = c & 63;
            outp[(((size_t)bb * NH + h) * NL + l) * NHD + d] = acc[i][j];
        }
    }
}

// QR = q[b,h] @ rel_emb[0:NL]^T   (NT GEMM, K=64). Skips tiles fully outside
// the causal band k >= NL-1-i.
__global__ void __launch_bounds__(256, 2) gemm_qr(const float* __restrict__ rel)
{
    const int m0 = blockIdx.y * 128;   // query rows i
    const int n0 = blockIdx.x * 128;   // rel cols k
    if (m0 + n0 + 254 < NL - 1) return;   // never read by attention
    const int bh = blockIdx.z;
    __shared__ float As[8][128];
    __shared__ float Bs[8][128];
    const float* A = g_q + (size_t)bh * NL * NHD;
    const int tid  = threadIdx.x;
    const int trow = tid >> 4, tcol = tid & 15;
    const int arow = tid >> 1, acol = (tid & 1) * 4;
    float acc[8][8] = {};
    for (int k0 = 0; k0 < NHD; k0 += 8) {
        float4 av = *(const float4*)&A[(size_t)(m0 + arow) * NHD + k0 + acol];
        float4 bv = *(const float4*)&rel[(size_t)(n0 + arow) * NHD + k0 + acol];
        __syncthreads();
        As[acol + 0][arow] = av.x;
        As[acol + 1][arow] = av.y;
        As[acol + 2][arow] = av.z;
        As[acol + 3][arow] = av.w;
        Bs[acol + 0][arow] = bv.x;
        Bs[acol + 1][arow] = bv.y;
        Bs[acol + 2][arow] = bv.z;
        Bs[acol + 3][arow] = bv.w;
        __syncthreads();
#pragma unroll
        for (int k = 0; k < 8; k++) {
            float a[8], b[8];
            *(float4*)&a[0] = *(const float4*)&As[k][trow * 8];
            *(float4*)&a[4] = *(const float4*)&As[k][trow * 8 + 4];
            *(float4*)&b[0] = *(const float4*)&Bs[k][tcol * 8];
            *(float4*)&b[4] = *(const float4*)&Bs[k][tcol * 8 + 4];
#pragma unroll
            for (int i = 0; i < 8; i++)
#pragma unroll
                for (int j = 0; j < 8; j++)
                    acc[i][j] = fmaf(a[i], b[j], acc[i][j]);
        }
    }
    float* outp = g_qr + (size_t)bh * NL * NL;
#pragma unroll
    for (int i = 0; i < 8; i++) {
        int m = m0 + trow * 8 + i;
#pragma unroll
        for (int j = 0; j < 8; j++)
            outp[(size_t)m * NL + n0 + tcol * 8 + j] = acc[i][j];
    }
}

__global__ void __launch_bounds__(256, 2) gemm_out(
    const float* __restrict__ Wo, const float* __restrict__ bo,
    float* __restrict__ out)
{
    __shared__ float As[8][128];
    __shared__ float Bs[8][128];
    const int m0 = blockIdx.y * 128;
    const int n0 = blockIdx.x * 128;
    const int tid  = threadIdx.x;
    const int trow = tid >> 4, tcol = tid & 15;
    const int arow = tid >> 1, acol = (tid & 1) * 4;
    const int brow = tid >> 5, bcol = (tid & 31) * 4;
    float acc[8][8] = {};
    for (int k0 = 0; k0 < NDOUT; k0 += 8) {
        float4 av = *(const float4*)&g_ctx[(size_t)(m0 + arow) * NDOUT + k0 + acol];
        float4 bv = *(const float4*)&Wo[(size_t)(k0 + brow) * NDOUT + n0 + bcol];
        __syncthreads();
        As[acol + 0][arow] = av.x;
        As[acol + 1][arow] = av.y;
        As[acol + 2][arow] = av.z;
        As[acol + 3][arow] = av.w;
        *(float4*)&Bs[brow][bcol] = bv;
        __syncthreads();
#pragma unroll
        for (int k = 0; k < 8; k++) {
            float a[8], b[8];
            *(float4*)&a[0] = *(const float4*)&As[k][trow * 8];
            *(float4*)&a[4] = *(const float4*)&As[k][trow * 8 + 4];
            *(float4*)&b[0] = *(const float4*)&Bs[k][tcol * 8];
            *(float4*)&b[4] = *(const float4*)&Bs[k][tcol * 8 + 4];
#pragma unroll
            for (int i = 0; i < 8; i++)
#pragma unroll
                for (int j = 0; j < 8; j++)
                    acc[i][j] = fmaf(a[i], b[j], acc[i][j]);
        }
    }
#pragma unroll
    for (int i = 0; i < 8; i++) {
        int m = m0 + trow * 8 + i;
#pragma unroll
        for (int j = 0; j < 8; j++) {
            int c = n0 + tcol * 8 + j;
            out[(size_t)m * NDOUT + c] = acc[i][j] + bo[c];
        }
    }
}

// ---------------------------------------------------------------------------
// Flash attention: 64-query tile per block, 64-key inner tiles, causal,
// online softmax, rel-bias gathered from g_qr. 256 threads, 4x4 per thread.
// Smem layouts: Qs/Ks are d-major [64][65] (fragment loads broadcast across
// half-warp), Vs is j-major [64][68] (float4 stores), Ps j-major [64][65].
// ---------------------------------------------------------------------------

#define ATT_SMEM_FLOATS (64 * 65 * 3 + 64 * 68)
#define ATT_SMEM_BYTES  (ATT_SMEM_FLOATS * 4)

__global__ void __launch_bounds__(256, 2) attn_kernel()
{
    extern __shared__ float sm[];
    float* Qs = sm;                  // [d][ii]  stride 65
    float* Ks = Qs + 64 * 65;        // [d][jj]  stride 65
    float* Vs = Ks + 64 * 65;        // [j][dd]  stride 68
    float* Ps = Vs + 64 * 68;        // [j][ii]  stride 65

    const int i0 = blockIdx.x * 64;
    const int bh = blockIdx.y;
    const int b  = bh >> 4, h = bh & 15;
    const int tid = threadIdx.x;
    const int ty = tid >> 4, tx = tid & 15;

    const float* qg = g_q + ((size_t)bh * NL + i0) * NHD;
#pragma unroll
    for (int t = 0; t < 4; t++) {
        int lin = tid + t * 256;
        int row = lin >> 4, d4 = (lin & 15) * 4;
        float4 v = *(const float4*)&qg[(size_t)row * NHD + d4];
        Qs[(d4 + 0) * 65 + row] = v.x;
        Qs[(d4 + 1) * 65 + row] = v.y;
        Qs[(d4 + 2) * 65 + row] = v.z;
        Qs[(d4 + 3) * 65 + row] = v.w;
    }

    float m_[4], l_[4], O[4][4];
#pragma unroll
    for (int i = 0; i < 4; i++) {
        m_[i] = -1e30f; l_[i] = 0.f;
#pragma unroll
        for (int j = 0; j < 4; j++) O[i][j] = 0.f;
    }
    const float* qr_base = g_qr + (size_t)bh * NL * NL;

    for (int j0 = 0; j0 <= i0; j0 += 64) {
        __syncthreads();   // previous iteration done with Ks/Vs/Ps
        const float* kg = g_k + ((size_t)bh * NL + j0) * NHD;
        const float* vg = g_v + ((size_t)bh * NL + j0) * NHD;
#pragma unroll
        for (int t = 0; t < 4; t++) {
            int lin = tid + t * 256;
            int row = lin >> 4, d4 = (lin & 15) * 4;
            float4 kv = *(const float4*)&kg[(size_t)row * NHD + d4];
            Ks[(d4 + 0) * 65 + row] = kv.x;
            Ks[(d4 + 1) * 65 + row] = kv.y;
            Ks[(d4 + 2) * 65 + row] = kv.z;
            Ks[(d4 + 3) * 65 + row] = kv.w;
            float4 vv = *(const float4*)&vg[(size_t)row * NHD + d4];
            *(float4*)&Vs[row * 68 + d4] = vv;
        }
        __syncthreads();

        // S = Q K^T (4x4 per thread)
        float S[4][4];
#pragma unroll
        for (int i = 0; i < 4; i++)
#pragma unroll
            for (int j = 0; j < 4; j++) S[i][j] = 0.f;
#pragma unroll 8
        for (int d = 0; d < 64; d++) {
            float qv[4], kv[4];
#pragma unroll
            for (int i = 0; i < 4; i++) qv[i] = Qs[d * 65 + ty * 4 + i];
#pragma unroll
            for (int j = 0; j < 4; j++) kv[j] = Ks[d * 65 + tx * 4 + j];
#pragma unroll
            for (int i = 0; i < 4; i++)
#pragma unroll
                for (int j = 0; j < 4; j++)
                    S[i][j] = fmaf(qv[i], kv[j], S[i][j]);
        }

        // rel bias gather + scale + causal mask
#pragma unroll
        for (int i = 0; i < 4; i++) {
            int gi = i0 + ty * 4 + i;
            const float* qr_row = qr_base + (size_t)gi * NL;
#pragma unroll
            for (int j = 0; j < 4; j++) {
                int jg = j0 + tx * 4 + j;
                bool masked = jg > gi;
                int k = jg - gi + (NL - 1);        // in [0, NL-1] when unmasked
                float bias = qr_row[masked ? 0 : k];
                float s = (S[i][j] + bias) * 0.125f;
                S[i][j] = masked ? -1e30f : s;
            }
        }

        // online softmax (row groups = 16 consecutive lanes)
#pragma unroll
        for (int i = 0; i < 4; i++) {
            float mt = fmaxf(fmaxf(S[i][0], S[i][1]), fmaxf(S[i][2], S[i][3]));
#pragma unroll
            for (int s = 8; s >= 1; s >>= 1)
                mt = fmaxf(mt, __shfl_xor_sync(0xffffffffu, mt, s));
            float mn    = fmaxf(m_[i], mt);
            float alpha = __expf(m_[i] - mn);
            m_[i] = mn;
            float rs = 0.f;
#pragma unroll
            for (int j = 0; j < 4; j++) {
                float p = __expf(S[i][j] - mn);
                S[i][j] = p;
                rs += p;
            }
#pragma unroll
            for (int s = 8; s >= 1; s >>= 1)
                rs += __shfl_xor_sync(0xffffffffu, rs, s);
            l_[i] = l_[i] * alpha + rs;
#pragma unroll
            for (int j = 0; j < 4; j++) O[i][j] *= alpha;
        }

        // P -> smem (transposed to j-major)
#pragma unroll
        for (int i = 0; i < 4; i++)
#pragma unroll
            for (int j = 0; j < 4; j++)
                Ps[(tx * 4 + j) * 65 + ty * 4 + i] = S[i][j];
        __syncthreads();

        // O += P V (4x4 per thread, cols = d)
#pragma unroll 8
        for (int j = 0; j < 64; j++) {
            float pv[4], vv[4];
#pragma unroll
            for (int i = 0; i < 4; i++) pv[i] = Ps[j * 65 + ty * 4 + i];
#pragma unroll
            for (int jj = 0; jj < 4; jj++) vv[jj] = Vs[j * 68 + tx * 4 + jj];
#pragma unroll
            for (int i = 0; i < 4; i++)
#pragma unroll
                for (int jj = 0; jj < 4; jj++)
                    O[i][jj] = fmaf(pv[i], vv[jj], O[i][jj]);
        }
    }

    // epilogue: ctx[b, l, h*64 + d]
#pragma unroll
    for (int i = 0; i < 4; i++) {
        int gi = i0 + ty * 4 + i;
        float inv = 1.0f / l_[i];
#pragma unroll
        for (int j = 0; j < 4; j++)
            g_ctx[((size_t)b * NL + gi) * NDOUT + h * NHD + tx * 4 + j] = O[i][j] * inv;
    }
}

// ---------------------------------------------------------------------------

extern "C" void kernel_launch(void* const* d_in, const int* in_sizes, int n_in,
                              void* d_out, int out_size)
{
    const float* x   = (const float*)d_in[0];
    const float* Wq  = (const float*)d_in[1];
    const float* Wk  = (const float*)d_in[2];
    const float* Wv  = (const float*)d_in[3];
    const float* Wo  = (const float*)d_in[4];
    const float* bo  = (const float*)d_in[5];
    const float* rel = (const float*)d_in[6];
    float* out = (float*)d_out;

    cudaFuncSetAttribute(attn_kernel,
                         cudaFuncAttributeMaxDynamicSharedMemorySize,
                         ATT_SMEM_BYTES);

    gemm_qkv<<<dim3(8, 32, 3), 256>>>(x, Wq, Wk, Wv);
    gemm_qr <<<dim3(16, 16, NBH), 256>>>(rel);
    attn_kernel<<<dim3(NL / 64, NBH), 256, ATT_SMEM_BYTES>>>();
    gemm_out<<<dim3(8, 32), 256>>>(Wo, bo, out);
}

// round 7
// speedup vs baseline: 1.4479x; 1.4479x over previous
#include <cuda_runtime.h>
#include <cuda_bf16.h>
#include <cstdint>
#include <math.h>

#define NB    2
#define NL    2048
#define NDIN  1024
#define NDOUT 1024
#define NH    16
#define NHD   64
#define NBH   (NB * NH)

// ---------------------------------------------------------------------------
// Static scratch. RULE: these symbols are ONLY referenced from device code.
// Passing them as kernel arguments from host is UB and was the R3-R6 failure.
// ---------------------------------------------------------------------------
__device__ float g_q[NBH * NL * NHD];               // fp32 [b,h,l,d]
__device__ float g_k[NBH * NL * NHD];
__device__ float g_v[NBH * NL * NHD];
__device__ float g_ctx[NB * NL * NDOUT];            // attention output fp32
__device__ float g_qr[(size_t)NBH * NL * NL];       // [bh,i,k] causal band

__device__ __nv_bfloat16 g_xhi[NB * NL * NDIN];
__device__ __nv_bfloat16 g_xlo[NB * NL * NDIN];
__device__ __nv_bfloat16 g_wqthi[NDOUT * NDIN];     // W^T splits [N,K]
__device__ __nv_bfloat16 g_wqtlo[NDOUT * NDIN];
__device__ __nv_bfloat16 g_wkthi[NDOUT * NDIN];
__device__ __nv_bfloat16 g_wktlo[NDOUT * NDIN];
__device__ __nv_bfloat16 g_wvthi[NDOUT * NDIN];
__device__ __nv_bfloat16 g_wvtlo[NDOUT * NDIN];
__device__ __nv_bfloat16 g_wothi[NDOUT * NDOUT];
__device__ __nv_bfloat16 g_wotlo[NDOUT * NDOUT];
__device__ __nv_bfloat16 g_qhi[NBH * NL * NHD];     // q split (for QR gemm)
__device__ __nv_bfloat16 g_qlo[NBH * NL * NHD];
__device__ __nv_bfloat16 g_relhi[NL * NHD];         // rel_emb rows 0..2047
__device__ __nv_bfloat16 g_rello[NL * NHD];
__device__ __nv_bfloat16 g_ctxhi[NB * NL * NDOUT];  // ctx split
__device__ __nv_bfloat16 g_ctxlo[NB * NL * NDOUT];

// ---------------------------------------------------------------------------
// Warp-MMA primitives (sm_80+ features, valid on plain sm_100 target)
// ---------------------------------------------------------------------------
__device__ __forceinline__ uint32_t smem_u32(const void* p) {
    uint32_t a;
    asm("{ .reg .u64 t; cvta.to.shared.u64 t, %1; cvt.u32.u64 %0, t; }" : "=r"(a) : "l"(p));
    return a;
}
__device__ __forceinline__ void ldsm_x4(uint32_t& r0, uint32_t& r1, uint32_t& r2,
                                        uint32_t& r3, uint32_t addr) {
    asm volatile("ldmatrix.sync.aligned.m8n8.x4.shared.b16 {%0,%1,%2,%3}, [%4];"
                 : "=r"(r0), "=r"(r1), "=r"(r2), "=r"(r3) : "r"(addr));
}
__device__ __forceinline__ void mma_bf16(
    float& d0, float& d1, float& d2, float& d3,
    uint32_t a0, uint32_t a1, uint32_t a2, uint32_t a3,
    uint32_t b0, uint32_t b1)
{
    asm volatile("mma.sync.aligned.m16n8k16.row.col.f32.bf16.bf16.f32 "
                 "{%0,%1,%2,%3}, {%4,%5,%6,%7}, {%8,%9}, {%0,%1,%2,%3};"
                 : "+f"(d0), "+f"(d1), "+f"(d2), "+f"(d3)
                 : "r"(a0), "r"(a1), "r"(a2), "r"(a3), "r"(b0), "r"(b1));
}

// ---------------------------------------------------------------------------
// Monolithic bf16-split GEMM body (macro-expanded; no function boundaries).
// Block tile D[128,64] = A[128,K] · B[64,K]^T; 8 warps, warp tile 32x32.
// Split-3: Ahi*Bhi + Ahi*Blo + Alo*Bhi  (fp32-level accuracy).
// ---------------------------------------------------------------------------
#define BK      32
#define ROWB    80
#define SA_HI   0
#define SA_LO   (128 * ROWB)
#define SB_HI   (2 * 128 * ROWB)
#define SB_LO   (SB_HI + 64 * ROWB)
#define SM_TOT  (SB_LO + 64 * ROWB)      // 30720 B static shared

#define MMA3(C, AH, AL, BH0, BH1, BL0, BL1) do {                                   \
    mma_bf16((C).x,(C).y,(C).z,(C).w,(AH).x,(AH).y,(AH).z,(AH).w,(BH0),(BH1));     \
    mma_bf16((C).x,(C).y,(C).z,(C).w,(AH).x,(AH).y,(AH).z,(AH).w,(BL0),(BL1));     \
    mma_bf16((C).x,(C).y,(C).z,(C).w,(AL).x,(AL).y,(AL).z,(AL).w,(BH0),(BH1));     \
} while (0)

#define KSTEP(KS, MF, C0, C1, C2, C3) do {                                         \
    uint32_t aoff = (uint32_t)(wm + (MF) * 16 + (lane & 15)) * ROWB                \
                  + (KS) * 32 + (lane >> 4) * 16;                                  \
    uint4 aH, aL;                                                                  \
    ldsm_x4(aH.x, aH.y, aH.z, aH.w, sb + SA_HI + aoff);                            \
    ldsm_x4(aL.x, aL.y, aL.z, aL.w, sb + SA_LO + aoff);                            \
    if ((KS) == 0) {                                                               \
        MMA3(C0, aH, aL, bh0.x, bh0.y, bl0.x, bl0.y);                              \
        MMA3(C1, aH, aL, bh1.x, bh1.y, bl1.x, bl1.y);                              \
        MMA3(C2, aH, aL, bh2.x, bh2.y, bl2.x, bl2.y);                              \
        MMA3(C3, aH, aL, bh3.x, bh3.y, bl3.x, bl3.y);                              \
    } else {                                                                       \
        MMA3(C0, aH, aL, bh0.z, bh0.w, bl0.z, bl0.w);                              \
        MMA3(C1, aH, aL, bh1.z, bh1.w, bl1.z, bl1.w);                              \
        MMA3(C2, aH, aL, bh2.z, bh2.w, bl2.z, bl2.w);                              \
        MMA3(C3, aH, aL, bh3.z, bh3.w, bl3.z, bl3.w);                              \
    }                                                                              \
} while (0)

#define GEMM_BODY(AHI, ALO, BHI, BLO, LDA, LDB, NCH, AROW0, BROW0)                 \
    __shared__ char smem[SM_TOT];                                                  \
    const uint32_t sb = smem_u32(smem);                                            \
    const int tid = threadIdx.x;                                                   \
    const int lane = tid & 31;                                                     \
    const int wid = tid >> 5;                                                      \
    const int wm = (wid & 3) * 32;                                                 \
    const int wn = (wid >> 2) * 32;                                                \
    float4 c00 = make_float4(0.f, 0.f, 0.f, 0.f);                                  \
    float4 c01 = c00, c02 = c00, c03 = c00;                                        \
    float4 c10 = c00, c11 = c00, c12 = c00, c13 = c00;                             \
    for (int ch = 0; ch < (NCH); ch++) {                                           \
        const int k0 = ch * BK;                                                    \
        __syncthreads();                                                           \
        {                                                                          \
            int row = tid >> 2, cc4 = tid & 3;                                     \
            *(uint4*)(smem + SA_HI + row * ROWB + cc4 * 16) =                      \
                *(const uint4*)((AHI) + (size_t)((AROW0) + row) * (LDA) + k0 + cc4 * 8); \
            *(uint4*)(smem + SA_LO + row * ROWB + cc4 * 16) =                      \
                *(const uint4*)((ALO) + (size_t)((AROW0) + row) * (LDA) + k0 + cc4 * 8); \
            *(uint4*)(smem + SA_HI + (row + 64) * ROWB + cc4 * 16) =               \
                *(const uint4*)((AHI) + (size_t)((AROW0) + row + 64) * (LDA) + k0 + cc4 * 8); \
            *(uint4*)(smem + SA_LO + (row + 64) * ROWB + cc4 * 16) =               \
                *(const uint4*)((ALO) + (size_t)((AROW0) + row + 64) * (LDA) + k0 + cc4 * 8); \
            *(uint4*)(smem + SB_HI + row * ROWB + cc4 * 16) =                      \
                *(const uint4*)((BHI) + (size_t)((BROW0) + row) * (LDB) + k0 + cc4 * 8); \
            *(uint4*)(smem + SB_LO + row * ROWB + cc4 * 16) =                      \
                *(const uint4*)((BLO) + (size_t)((BROW0) + row) * (LDB) + k0 + cc4 * 8); \
        }                                                                          \
        __syncthreads();                                                           \
        uint4 bh0, bh1, bh2, bh3, bl0, bl1, bl2, bl3;                              \
        {                                                                          \
            uint32_t boff = (uint32_t)(wn + (lane & 7)) * ROWB + (lane >> 3) * 16; \
            ldsm_x4(bh0.x, bh0.y, bh0.z, bh0.w, sb + SB_HI + boff);                \
            ldsm_x4(bl0.x, bl0.y, bl0.z, bl0.w, sb + SB_LO + boff);                \
            ldsm_x4(bh1.x, bh1.y, bh1.z, bh1.w, sb + SB_HI + boff + 8 * ROWB);     \
            ldsm_x4(bl1.x, bl1.y, bl1.z, bl1.w, sb + SB_LO + boff + 8 * ROWB);     \
            ldsm_x4(bh2.x, bh2.y, bh2.z, bh2.w, sb + SB_HI + boff + 16 * ROWB);    \
            ldsm_x4(bl2.x, bl2.y, bl2.z, bl2.w, sb + SB_LO + boff + 16 * ROWB);    \
            ldsm_x4(bh3.x, bh3.y, bh3.z, bh3.w, sb + SB_HI + boff + 24 * ROWB);    \
            ldsm_x4(bl3.x, bl3.y, bl3.z, bl3.w, sb + SB_LO + boff + 24 * ROWB);    \
        }                                                                          \
        KSTEP(0, 0, c00, c01, c02, c03);                                           \
        KSTEP(0, 1, c10, c11, c12, c13);                                           \
        KSTEP(1, 0, c00, c01, c02, c03);                                           \
        KSTEP(1, 1, c10, c11, c12, c13);                                           \
    }

// index into [b,h,l,d] layout from (m = b*NL+l, col = h*64+d)
#define QKV_IDX(m, col) \
    ((((size_t)((m) >> 11) * NH + ((col) >> 6)) * NL + ((m) & (NL - 1))) * NHD + ((col) & 63))

#define QSPLIT(idx, v0, v1) do {                                                   \
    __nv_bfloat16 _h0 = __float2bfloat16(v0), _h1 = __float2bfloat16(v1);          \
    g_qhi[idx] = _h0; g_qhi[(idx) + 1] = _h1;                                      \
    g_qlo[idx]       = __float2bfloat16((v0) - __bfloat162float(_h0));             \
    g_qlo[(idx) + 1] = __float2bfloat16((v1) - __bfloat162float(_h1));             \
} while (0)

// ---------------------------------------------------------------------------
// Prep kernels — globals touched ONLY in device code
// ---------------------------------------------------------------------------
__global__ void prep_split_x(const float* __restrict__ x)
{
    int i = (blockIdx.x * blockDim.x + threadIdx.x) * 4;
    float4 v = *(const float4*)(x + i);
    __nv_bfloat16 h0 = __float2bfloat16(v.x);
    __nv_bfloat16 h1 = __float2bfloat16(v.y);
    __nv_bfloat16 h2 = __float2bfloat16(v.z);
    __nv_bfloat16 h3 = __float2bfloat16(v.w);
    g_xhi[i + 0] = h0; g_xhi[i + 1] = h1; g_xhi[i + 2] = h2; g_xhi[i + 3] = h3;
    g_xlo[i + 0] = __float2bfloat16(v.x - __bfloat162float(h0));
    g_xlo[i + 1] = __float2bfloat16(v.y - __bfloat162float(h1));
    g_xlo[i + 2] = __float2bfloat16(v.z - __bfloat162float(h2));
    g_xlo[i + 3] = __float2bfloat16(v.w - __bfloat162float(h3));
}

__global__ void prep_split_rel(const float* __restrict__ rel)
{
    int i = (blockIdx.x * blockDim.x + threadIdx.x) * 4;
    float4 v = *(const float4*)(rel + i);
    __nv_bfloat16 h0 = __float2bfloat16(v.x);
    __nv_bfloat16 h1 = __float2bfloat16(v.y);
    __nv_bfloat16 h2 = __float2bfloat16(v.z);
    __nv_bfloat16 h3 = __float2bfloat16(v.w);
    g_relhi[i + 0] = h0; g_relhi[i + 1] = h1; g_relhi[i + 2] = h2; g_relhi[i + 3] = h3;
    g_rello[i + 0] = __float2bfloat16(v.x - __bfloat162float(h0));
    g_rello[i + 1] = __float2bfloat16(v.y - __bfloat162float(h1));
    g_rello[i + 2] = __float2bfloat16(v.z - __bfloat162float(h2));
    g_rello[i + 3] = __float2bfloat16(v.w - __bfloat162float(h3));
}

__global__ void split_ctx()
{
    int i = (blockIdx.x * blockDim.x + threadIdx.x) * 4;
    float4 v = *(const float4*)(g_ctx + i);
    __nv_bfloat16 h0 = __float2bfloat16(v.x);
    __nv_bfloat16 h1 = __float2bfloat16(v.y);
    __nv_bfloat16 h2 = __float2bfloat16(v.z);
    __nv_bfloat16 h3 = __float2bfloat16(v.w);
    g_ctxhi[i + 0] = h0; g_ctxhi[i + 1] = h1; g_ctxhi[i + 2] = h2; g_ctxhi[i + 3] = h3;
    g_ctxlo[i + 0] = __float2bfloat16(v.x - __bfloat162float(h0));
    g_ctxlo[i + 1] = __float2bfloat16(v.y - __bfloat162float(h1));
    g_ctxlo[i + 2] = __float2bfloat16(v.z - __bfloat162float(h2));
    g_ctxlo[i + 3] = __float2bfloat16(v.w - __bfloat162float(h3));
}

__global__ void prep_wt(const float* __restrict__ Wq, const float* __restrict__ Wk,
                        const float* __restrict__ Wv, const float* __restrict__ Wo)
{
    __shared__ float t[32][33];
    const int z = blockIdx.z;
    const float* W = (z == 0) ? Wq : (z == 1) ? Wk : (z == 2) ? Wv : Wo;
    __nv_bfloat16* Th = (z == 0) ? g_wqthi : (z == 1) ? g_wkthi : (z == 2) ? g_wvthi : g_wothi;
    __nv_bfloat16* Tl = (z == 0) ? g_wqtlo : (z == 1) ? g_wktlo : (z == 2) ? g_wvtlo : g_wotlo;
    const int x0 = blockIdx.x * 32, y0 = blockIdx.y * 32;
    const int tx = threadIdx.x, ty = threadIdx.y;
#pragma unroll
    for (int j = 0; j < 4; j++)
        t[ty + 8 * j][tx] = W[(size_t)(y0 + ty + 8 * j) * 1024 + x0 + tx];
    __syncthreads();
#pragma unroll
    for (int j = 0; j < 4; j++) {
        float v = t[tx][ty + 8 * j];
        __nv_bfloat16 h = __float2bfloat16(v);
        size_t idx = (size_t)(x0 + ty + 8 * j) * 1024 + y0 + tx;
        Th[idx] = h;
        Tl[idx] = __float2bfloat16(v - __bfloat162float(h));
    }
}

// ---------------------------------------------------------------------------
// MMA GEMM kernels (monolithic)
// ---------------------------------------------------------------------------
__global__ void __launch_bounds__(256) tc_gemm_qkv()
{
    const int n0 = blockIdx.x * 64;
    const int m0 = blockIdx.y * 128;
    const int z  = blockIdx.z;
    const __nv_bfloat16* Bh = (z == 0) ? g_wqthi : (z == 1) ? g_wkthi : g_wvthi;
    const __nv_bfloat16* Bl = (z == 0) ? g_wqtlo : (z == 1) ? g_wktlo : g_wvtlo;
    GEMM_BODY(g_xhi, g_xlo, Bh, Bl, NDIN, NDIN, NDIN / BK, m0, n0)

    float* outp = (z == 0) ? g_q : (z == 1) ? g_k : g_v;
    const int mb = m0 + wm + (lane >> 2);
    const int cb = n0 + wn + (lane & 3) * 2;
#define EP_QKV(C, MO, CO) do {                                                     \
    int m = mb + (MO), col = cb + (CO);                                            \
    size_t idx = QKV_IDX(m, col);                                                  \
    *(float2*)(outp + idx) = make_float2((C).x, (C).y);                            \
    if (z == 0) QSPLIT(idx, (C).x, (C).y);                                         \
    idx = QKV_IDX(m + 8, col);                                                     \
    *(float2*)(outp + idx) = make_float2((C).z, (C).w);                            \
    if (z == 0) QSPLIT(idx, (C).z, (C).w);                                         \
} while (0)
    EP_QKV(c00, 0, 0);  EP_QKV(c01, 0, 8);  EP_QKV(c02, 0, 16);  EP_QKV(c03, 0, 24);
    EP_QKV(c10, 16, 0); EP_QKV(c11, 16, 8); EP_QKV(c12, 16, 16); EP_QKV(c13, 16, 24);
#undef EP_QKV
}

__global__ void __launch_bounds__(256) tc_gemm_qr()
{
    const int n0 = blockIdx.x * 64;
    const int m0 = blockIdx.y * 128;
    if (m0 + n0 < 1857) return;              // tile fully outside causal band
    const int bh = blockIdx.z;
    const __nv_bfloat16* Ah = g_qhi + (size_t)bh * NL * NHD;
    const __nv_bfloat16* Al = g_qlo + (size_t)bh * NL * NHD;
    GEMM_BODY(Ah, Al, g_relhi, g_rello, NHD, NHD, NHD / BK, m0, n0)

    float* dst = g_qr + (size_t)bh * NL * NL;
    const int mb = m0 + wm + (lane >> 2);
    const int cb = n0 + wn + (lane & 3) * 2;
#define EP_QR(C, MO, CO) do {                                                      \
    int m = mb + (MO), col = cb + (CO);                                            \
    *(float2*)(dst + (size_t)m * NL + col)       = make_float2((C).x, (C).y);      \
    *(float2*)(dst + (size_t)(m + 8) * NL + col) = make_float2((C).z, (C).w);      \
} while (0)
    EP_QR(c00, 0, 0);  EP_QR(c01, 0, 8);  EP_QR(c02, 0, 16);  EP_QR(c03, 0, 24);
    EP_QR(c10, 16, 0); EP_QR(c11, 16, 8); EP_QR(c12, 16, 16); EP_QR(c13, 16, 24);
#undef EP_QR
}

__global__ void __launch_bounds__(256) tc_gemm_out(
    const float* __restrict__ bo, float* __restrict__ out)
{
    const int n0 = blockIdx.x * 64;
    const int m0 = blockIdx.y * 128;
    GEMM_BODY(g_ctxhi, g_ctxlo, g_wothi, g_wotlo, NDOUT, NDOUT, NDOUT / BK, m0, n0)

    const int mb = m0 + wm + (lane >> 2);
    const int cb = n0 + wn + (lane & 3) * 2;
#define EP_OUT(C, MO, CO) do {                                                     \
    int m = mb + (MO), col = cb + (CO);                                            \
    float b0 = bo[col], b1 = bo[col + 1];                                          \
    *(float2*)(out + (size_t)m * NDOUT + col) =                                    \
        make_float2((C).x + b0, (C).y + b1);                                       \
    *(float2*)(out + (size_t)(m + 8) * NDOUT + col) =                              \
        make_float2((C).z + b0, (C).w + b1);                                       \
} while (0)
    EP_OUT(c00, 0, 0);  EP_OUT(c01, 0, 8);  EP_OUT(c02, 0, 16);  EP_OUT(c03, 0, 24);
    EP_OUT(c10, 16, 0); EP_OUT(c11, 16, 8); EP_OUT(c12, 16, 16); EP_OUT(c13, 16, 24);
#undef EP_OUT
}

// ---------------------------------------------------------------------------
// Flash attention — byte-identical to the R1 kernel that passed (fp32)
// ---------------------------------------------------------------------------
#define ATT_SMEM_FLOATS (64 * 65 * 3 + 64 * 68)
#define ATT_SMEM_BYTES  (ATT_SMEM_FLOATS * 4)

__global__ void __launch_bounds__(256, 2) attn_kernel()
{
    extern __shared__ float sm[];
    float* Qs = sm;                  // [d][ii]  stride 65
    float* Ks = Qs + 64 * 65;        // [d][jj]  stride 65
    float* Vs = Ks + 64 * 65;        // [j][dd]  stride 68
    float* Ps = Vs + 64 * 68;        // [j][ii]  stride 65

    const int i0 = blockIdx.x * 64;
    const int bh = blockIdx.y;
    const int b  = bh >> 4, h = bh & 15;
    const int tid = threadIdx.x;
    const int ty = tid >> 4, tx = tid & 15;

    const float* qg = g_q + ((size_t)bh * NL + i0) * NHD;
#pragma unroll
    for (int t = 0; t < 4; t++) {
        int lin = tid + t * 256;
        int row = lin >> 4, d4 = (lin & 15) * 4;
        float4 v = *(const float4*)&qg[(size_t)row * NHD + d4];
        Qs[(d4 + 0) * 65 + row] = v.x;
        Qs[(d4 + 1) * 65 + row] = v.y;
        Qs[(d4 + 2) * 65 + row] = v.z;
        Qs[(d4 + 3) * 65 + row] = v.w;
    }

    float m_[4], l_[4], O[4][4];
#pragma unroll
    for (int i = 0; i < 4; i++) {
        m_[i] = -1e30f; l_[i] = 0.f;
#pragma unroll
        for (int j = 0; j < 4; j++) O[i][j] = 0.f;
    }
    const float* qr_base = g_qr + (size_t)bh * NL * NL;

    for (int j0 = 0; j0 <= i0; j0 += 64) {
        __syncthreads();
        const float* kg = g_k + ((size_t)bh * NL + j0) * NHD;
        const float* vg = g_v + ((size_t)bh * NL + j0) * NHD;
#pragma unroll
        for (int t = 0; t < 4; t++) {
            int lin = tid + t * 256;
            int row = lin >> 4, d4 = (lin & 15) * 4;
            float4 kv = *(const float4*)&kg[(size_t)row * NHD + d4];
            Ks[(d4 + 0) * 65 + row] = kv.x;
            Ks[(d4 + 1) * 65 + row] = kv.y;
            Ks[(d4 + 2) * 65 + row] = kv.z;
            Ks[(d4 + 3) * 65 + row] = kv.w;
            float4 vv = *(const float4*)&vg[(size_t)row * NHD + d4];
            *(float4*)&Vs[row * 68 + d4] = vv;
        }
        __syncthreads();

        float S[4][4];
#pragma unroll
        for (int i = 0; i < 4; i++)
#pragma unroll
            for (int j = 0; j < 4; j++) S[i][j] = 0.f;
#pragma unroll 8
        for (int d = 0; d < 64; d++) {
            float qv[4], kv[4];
#pragma unroll
            for (int i = 0; i < 4; i++) qv[i] = Qs[d * 65 + ty * 4 + i];
#pragma unroll
            for (int j = 0; j < 4; j++) kv[j] = Ks[d * 65 + tx * 4 + j];
#pragma unroll
            for (int i = 0; i < 4; i++)
#pragma unroll
                for (int j = 0; j < 4; j++)
                    S[i][j] = fmaf(qv[i], kv[j], S[i][j]);
        }

#pragma unroll
        for (int i = 0; i < 4; i++) {
            int gi = i0 + ty * 4 + i;
            const float* qr_row = qr_base + (size_t)gi * NL;
#pragma unroll
            for (int j = 0; j < 4; j++) {
                int jg = j0 + tx * 4 + j;
                bool masked = jg > gi;
                int k = jg - gi + (NL - 1);
                float bias = qr_row[masked ? 0 : k];
                float s = (S[i][j] + bias) * 0.125f;
                S[i][j] = masked ? -1e30f : s;
            }
        }

#pragma unroll
        for (int i = 0; i < 4; i++) {
            float mt = fmaxf(fmaxf(S[i][0], S[i][1]), fmaxf(S[i][2], S[i][3]));
#pragma unroll
            for (int s = 8; s >= 1; s >>= 1)
                mt = fmaxf(mt, __shfl_xor_sync(0xffffffffu, mt, s));
            float mn    = fmaxf(m_[i], mt);
            float alpha = __expf(m_[i] - mn);
            m_[i] = mn;
            float rs = 0.f;
#pragma unroll
            for (int j = 0; j < 4; j++) {
                float p = __expf(S[i][j] - mn);
                S[i][j] = p;
                rs += p;
            }
#pragma unroll
            for (int s = 8; s >= 1; s >>= 1)
                rs += __shfl_xor_sync(0xffffffffu, rs, s);
            l_[i] = l_[i] * alpha + rs;
#pragma unroll
            for (int j = 0; j < 4; j++) O[i][j] *= alpha;
        }

#pragma unroll
        for (int i = 0; i < 4; i++)
#pragma unroll
            for (int j = 0; j < 4; j++)
                Ps[(tx * 4 + j) * 65 + ty * 4 + i] = S[i][j];
        __syncthreads();

#pragma unroll 8
        for (int j = 0; j < 64; j++) {
            float pv[4], vv[4];
#pragma unroll
            for (int i = 0; i < 4; i++) pv[i] = Ps[j * 65 + ty * 4 + i];
#pragma unroll
            for (int jj = 0; jj < 4; jj++) vv[jj] = Vs[j * 68 + tx * 4 + jj];
#pragma unroll
            for (int i = 0; i < 4; i++)
#pragma unroll
                for (int jj = 0; jj < 4; jj++)
                    O[i][jj] = fmaf(pv[i], vv[jj], O[i][jj]);
        }
    }

#pragma unroll
    for (int i = 0; i < 4; i++) {
        int gi = i0 + ty * 4 + i;
        float inv = 1.0f / l_[i];
#pragma unroll
        for (int j = 0; j < 4; j++)
            g_ctx[((size_t)b * NL + gi) * NDOUT + h * NHD + tx * 4 + j] = O[i][j] * inv;
    }
}

// ---------------------------------------------------------------------------

extern "C" void kernel_launch(void* const* d_in, const int* in_sizes, int n_in,
                              void* d_out, int out_size)
{
    const float* x   = (const float*)d_in[0];
    const float* Wq  = (const float*)d_in[1];
    const float* Wk  = (const float*)d_in[2];
    const float* Wv  = (const float*)d_in[3];
    const float* Wo  = (const float*)d_in[4];
    const float* bo  = (const float*)d_in[5];
    const float* rel = (const float*)d_in[6];
    float* out = (float*)d_out;

    cudaFuncSetAttribute(attn_kernel, cudaFuncAttributeMaxDynamicSharedMemorySize,
                         ATT_SMEM_BYTES);

    prep_split_x  <<<NB * NL * NDIN / 1024, 256>>>(x);
    prep_split_rel<<<NL * NHD / 1024, 256>>>(rel);
    prep_wt<<<dim3(32, 32, 4), dim3(32, 8)>>>(Wq, Wk, Wv, Wo);

    tc_gemm_qkv<<<dim3(NDOUT / 64, NB * NL / 128, 3), 256>>>();
    tc_gemm_qr <<<dim3(NL / 64, NL / 128, NBH), 256>>>();
    attn_kernel<<<dim3(NL / 64, NBH), 256, ATT_SMEM_BYTES>>>();
    split_ctx  <<<NB * NL * NDOUT / 1024, 256>>>();
    tc_gemm_out<<<dim3(NDOUT / 64, NB * NL / 128), 256>>>(bo, out);
}

// round 8
// speedup vs baseline: 1.8257x; 1.2610x over previous
#include <cuda_runtime.h>
#include <cuda_bf16.h>
#include <cstdint>
#include <math.h>

#define NB    2
#define NL    2048
#define NDIN  1024
#define NDOUT 1024
#define NH    16
#define NHD   64
#define NBH   (NB * NH)

// ---------------------------------------------------------------------------
// Static scratch. RULE: only referenced from device code, never passed as
// kernel arguments from host (that was the R3-R6 allocation-guard failure).
// ---------------------------------------------------------------------------
__device__ float g_v[NBH * NL * NHD];                       // fp32 [b,h,l,d]
__device__ float g_qr[(size_t)NBH * NL * NL];               // rel-bias GEMM (band)
__device__ float g_s[(size_t)NBH * NL * NL];                // scores (band)
__device__ __nv_bfloat16 g_phi[(size_t)NBH * NL * NL];      // softmax P split
__device__ __nv_bfloat16 g_plo[(size_t)NBH * NL * NL];

__device__ __nv_bfloat16 g_xhi[NB * NL * NDIN];
__device__ __nv_bfloat16 g_xlo[NB * NL * NDIN];
__device__ __nv_bfloat16 g_wqthi[NDOUT * NDIN];             // W^T splits [N,K]
__device__ __nv_bfloat16 g_wqtlo[NDOUT * NDIN];
__device__ __nv_bfloat16 g_wkthi[NDOUT * NDIN];
__device__ __nv_bfloat16 g_wktlo[NDOUT * NDIN];
__device__ __nv_bfloat16 g_wvthi[NDOUT * NDIN];
__device__ __nv_bfloat16 g_wvtlo[NDOUT * NDIN];
__device__ __nv_bfloat16 g_wothi[NDOUT * NDOUT];
__device__ __nv_bfloat16 g_wotlo[NDOUT * NDOUT];
__device__ __nv_bfloat16 g_qhi[NBH * NL * NHD];             // q split [bh][l][d]
__device__ __nv_bfloat16 g_qlo[NBH * NL * NHD];
__device__ __nv_bfloat16 g_khi[NBH * NL * NHD];             // k split [bh][l][d]
__device__ __nv_bfloat16 g_klo[NBH * NL * NHD];
__device__ __nv_bfloat16 g_vthi[NBH * NHD * NL];            // V^T split [bh][d][l]
__device__ __nv_bfloat16 g_vtlo[NBH * NHD * NL];
__device__ __nv_bfloat16 g_relhi[NL * NHD];
__device__ __nv_bfloat16 g_rello[NL * NHD];
__device__ __nv_bfloat16 g_ctxhi[NB * NL * NDOUT];
__device__ __nv_bfloat16 g_ctxlo[NB * NL * NDOUT];

// ---------------------------------------------------------------------------
// Warp-MMA primitives (sm_80+ features; plain sm_100 target)
// ---------------------------------------------------------------------------
__device__ __forceinline__ uint32_t smem_u32(const void* p) {
    uint32_t a;
    asm("{ .reg .u64 t; cvta.to.shared.u64 t, %1; cvt.u32.u64 %0, t; }" : "=r"(a) : "l"(p));
    return a;
}
__device__ __forceinline__ void ldsm_x4(uint32_t& r0, uint32_t& r1, uint32_t& r2,
                                        uint32_t& r3, uint32_t addr) {
    asm volatile("ldmatrix.sync.aligned.m8n8.x4.shared.b16 {%0,%1,%2,%3}, [%4];"
                 : "=r"(r0), "=r"(r1), "=r"(r2), "=r"(r3) : "r"(addr));
}
__device__ __forceinline__ void mma_bf16(
    float& d0, float& d1, float& d2, float& d3,
    uint32_t a0, uint32_t a1, uint32_t a2, uint32_t a3,
    uint32_t b0, uint32_t b1)
{
    asm volatile("mma.sync.aligned.m16n8k16.row.col.f32.bf16.bf16.f32 "
                 "{%0,%1,%2,%3}, {%4,%5,%6,%7}, {%8,%9}, {%0,%1,%2,%3};"
                 : "+f"(d0), "+f"(d1), "+f"(d2), "+f"(d3)
                 : "r"(a0), "r"(a1), "r"(a2), "r"(a3), "r"(b0), "r"(b1));
}
__device__ __forceinline__ void cp16(uint32_t dst, const void* src) {
    asm volatile("cp.async.cg.shared.global [%0], [%1], 16;" :: "r"(dst), "l"(src) : "memory");
}

// ---------------------------------------------------------------------------
// bf16-split GEMM body, cp.async 2-stage double buffer (macro; monolithic).
// Block tile D[128,64] = A[128,K] · B[64,K]^T; 8 warps, warp tile 32x32.
// Split-3: Ahi*Bhi + Ahi*Blo + Alo*Bhi.
// ---------------------------------------------------------------------------
#define BK      32
#define ROWB    80
#define SA_HI   0
#define SA_LO   (128 * ROWB)
#define SB_HI   (2 * 128 * ROWB)
#define SB_LO   (SB_HI + 64 * ROWB)
#define SM_STG  (SB_LO + 64 * ROWB)      // 30720 B per stage
#define SM_DYN  (2 * SM_STG)             // 61440 B dynamic shared

#define MMA3(C, AH, AL, BH0, BH1, BL0, BL1) do {                                   \
    mma_bf16((C).x,(C).y,(C).z,(C).w,(AH).x,(AH).y,(AH).z,(AH).w,(BH0),(BH1));     \
    mma_bf16((C).x,(C).y,(C).z,(C).w,(AH).x,(AH).y,(AH).z,(AH).w,(BL0),(BL1));     \
    mma_bf16((C).x,(C).y,(C).z,(C).w,(AL).x,(AL).y,(AL).z,(AL).w,(BH0),(BH1));     \
} while (0)

#define KSTEP(KS, MF, C0, C1, C2, C3) do {                                         \
    uint32_t aoff = (uint32_t)(wm + (MF) * 16 + (lane & 15)) * ROWB                \
                  + (KS) * 32 + (lane >> 4) * 16;                                  \
    uint4 aH, aL;                                                                  \
    ldsm_x4(aH.x, aH.y, aH.z, aH.w, sb + SA_HI + aoff);                            \
    ldsm_x4(aL.x, aL.y, aL.z, aL.w, sb + SA_LO + aoff);                            \
    if ((KS) == 0) {                                                               \
        MMA3(C0, aH, aL, bh0.x, bh0.y, bl0.x, bl0.y);                              \
        MMA3(C1, aH, aL, bh1.x, bh1.y, bl1.x, bl1.y);                              \
        MMA3(C2, aH, aL, bh2.x, bh2.y, bl2.x, bl2.y);                              \
        MMA3(C3, aH, aL, bh3.x, bh3.y, bl3.x, bl3.y);                              \
    } else {                                                                       \
        MMA3(C0, aH, aL, bh0.z, bh0.w, bl0.z, bl0.w);                              \
        MMA3(C1, aH, aL, bh1.z, bh1.w, bl1.z, bl1.w);                              \
        MMA3(C2, aH, aL, bh2.z, bh2.w, bl2.z, bl2.w);                              \
        MMA3(C3, aH, aL, bh3.z, bh3.w, bl3.z, bl3.w);                              \
    }                                                                              \
} while (0)

#define GEMM_ASYNC(AHI, ALO, BHI, BLO, LDA, LDB, NCHEXPR, AROW0, BROW0)            \
    extern __shared__ char dsm[];                                                  \
    const uint32_t sb0 = smem_u32(dsm);                                            \
    const int tid = threadIdx.x;                                                   \
    const int lane = tid & 31;                                                     \
    const int wid = tid >> 5;                                                      \
    const int wm = (wid & 3) * 32;                                                 \
    const int wn = (wid >> 2) * 32;                                                \
    const int prow = tid >> 2;                                                     \
    const int pc4 = tid & 3;                                                       \
    float4 c00 = make_float4(0.f, 0.f, 0.f, 0.f);                                  \
    float4 c01 = c00, c02 = c00, c03 = c00;                                        \
    float4 c10 = c00, c11 = c00, c12 = c00, c13 = c00;                             \
    const int nch_ = (NCHEXPR);                                                    \
    for (int ch = 0; ch <= nch_; ch++) {                                           \
        if (ch < nch_) {                                                           \
            const int k0 = ch * BK;                                                \
            const uint32_t db = sb0 + (uint32_t)(ch & 1) * SM_STG;                 \
            cp16(db + SA_HI + prow * ROWB + pc4 * 16,                              \
                 (AHI) + (size_t)((AROW0) + prow) * (LDA) + k0 + pc4 * 8);         \
            cp16(db + SA_LO + prow * ROWB + pc4 * 16,                              \
                 (ALO) + (size_t)((AROW0) + prow) * (LDA) + k0 + pc4 * 8);         \
            cp16(db + SA_HI + (prow + 64) * ROWB + pc4 * 16,                       \
                 (AHI) + (size_t)((AROW0) + prow + 64) * (LDA) + k0 + pc4 * 8);    \
            cp16(db + SA_LO + (prow + 64) * ROWB + pc4 * 16,                       \
                 (ALO) + (size_t)((AROW0) + prow + 64) * (LDA) + k0 + pc4 * 8);    \
            cp16(db + SB_HI + prow * ROWB + pc4 * 16,                              \
                 (BHI) + (size_t)((BROW0) + prow) * (LDB) + k0 + pc4 * 8);         \
            cp16(db + SB_LO + prow * ROWB + pc4 * 16,                              \
                 (BLO) + (size_t)((BROW0) + prow) * (LDB) + k0 + pc4 * 8);         \
            asm volatile("cp.async.commit_group;" ::: "memory");                   \
        }                                                                          \
        if (ch >= 1) {                                                             \
            if (ch < nch_) { asm volatile("cp.async.wait_group 1;" ::: "memory"); }\
            else           { asm volatile("cp.async.wait_group 0;" ::: "memory"); }\
            __syncthreads();                                                       \
            const uint32_t sb = sb0 + (uint32_t)((ch - 1) & 1) * SM_STG;           \
            uint4 bh0, bh1, bh2, bh3, bl0, bl1, bl2, bl3;                          \
            {                                                                      \
                uint32_t boff = (uint32_t)(wn + (lane & 7)) * ROWB + (lane >> 3) * 16; \
                ldsm_x4(bh0.x, bh0.y, bh0.z, bh0.w, sb + SB_HI + boff);            \
                ldsm_x4(bl0.x, bl0.y, bl0.z, bl0.w, sb + SB_LO + boff);            \
                ldsm_x4(bh1.x, bh1.y, bh1.z, bh1.w, sb + SB_HI + boff + 8 * ROWB); \
                ldsm_x4(bl1.x, bl1.y, bl1.z, bl1.w, sb + SB_LO + boff + 8 * ROWB); \
                ldsm_x4(bh2.x, bh2.y, bh2.z, bh2.w, sb + SB_HI + boff + 16 * ROWB);\
                ldsm_x4(bl2.x, bl2.y, bl2.z, bl2.w, sb + SB_LO + boff + 16 * ROWB);\
                ldsm_x4(bh3.x, bh3.y, bh3.z, bh3.w, sb + SB_HI + boff + 24 * ROWB);\
                ldsm_x4(bl3.x, bl3.y, bl3.z, bl3.w, sb + SB_LO + boff + 24 * ROWB);\
            }                                                                      \
            KSTEP(0, 0, c00, c01, c02, c03);                                       \
            KSTEP(0, 1, c10, c11, c12, c13);                                       \
            KSTEP(1, 0, c00, c01, c02, c03);                                       \
            KSTEP(1, 1, c10, c11, c12, c13);                                       \
            __syncthreads();                                                       \
        }                                                                          \
    }

// index into [b,h,l,d] from (m = b*NL+l, col = h*64+d)
#define QKV_IDX(m, col) \
    ((((size_t)((m) >> 11) * NH + ((col) >> 6)) * NL + ((m) & (NL - 1))) * NHD + ((col) & 63))

#define SPL(HI, LO, idx, v0, v1) do {                                              \
    __nv_bfloat16 _h0 = __float2bfloat16(v0), _h1 = __float2bfloat16(v1);          \
    (HI)[idx] = _h0; (HI)[(idx) + 1] = _h1;                                        \
    (LO)[idx]       = __float2bfloat16((v0) - __bfloat162float(_h0));              \
    (LO)[(idx) + 1] = __float2bfloat16((v1) - __bfloat162float(_h1));              \
} while (0)

// ---------------------------------------------------------------------------
// Prep kernels
// ---------------------------------------------------------------------------
__global__ void prep_split_x(const float* __restrict__ x)
{
    int i = (blockIdx.x * blockDim.x + threadIdx.x) * 4;
    float4 v = *(const float4*)(x + i);
    __nv_bfloat16 h0 = __float2bfloat16(v.x);
    __nv_bfloat16 h1 = __float2bfloat16(v.y);
    __nv_bfloat16 h2 = __float2bfloat16(v.z);
    __nv_bfloat16 h3 = __float2bfloat16(v.w);
    g_xhi[i + 0] = h0; g_xhi[i + 1] = h1; g_xhi[i + 2] = h2; g_xhi[i + 3] = h3;
    g_xlo[i + 0] = __float2bfloat16(v.x - __bfloat162float(h0));
    g_xlo[i + 1] = __float2bfloat16(v.y - __bfloat162float(h1));
    g_xlo[i + 2] = __float2bfloat16(v.z - __bfloat162float(h2));
    g_xlo[i + 3] = __float2bfloat16(v.w - __bfloat162float(h3));
}

__global__ void prep_split_rel(const float* __restrict__ rel)
{
    int i = (blockIdx.x * blockDim.x + threadIdx.x) * 4;
    float4 v = *(const float4*)(rel + i);
    __nv_bfloat16 h0 = __float2bfloat16(v.x);
    __nv_bfloat16 h1 = __float2bfloat16(v.y);
    __nv_bfloat16 h2 = __float2bfloat16(v.z);
    __nv_bfloat16 h3 = __float2bfloat16(v.w);
    g_relhi[i + 0] = h0; g_relhi[i + 1] = h1; g_relhi[i + 2] = h2; g_relhi[i + 3] = h3;
    g_rello[i + 0] = __float2bfloat16(v.x - __bfloat162float(h0));
    g_rello[i + 1] = __float2bfloat16(v.y - __bfloat162float(h1));
    g_rello[i + 2] = __float2bfloat16(v.z - __bfloat162float(h2));
    g_rello[i + 3] = __float2bfloat16(v.w - __bfloat162float(h3));
}

__global__ void prep_wt(const float* __restrict__ Wq, const float* __restrict__ Wk,
                        const float* __restrict__ Wv, const float* __restrict__ Wo)
{
    __shared__ float t[32][33];
    const int z = blockIdx.z;
    const float* W = (z == 0) ? Wq : (z == 1) ? Wk : (z == 2) ? Wv : Wo;
    __nv_bfloat16* Th = (z == 0) ? g_wqthi : (z == 1) ? g_wkthi : (z == 2) ? g_wvthi : g_wothi;
    __nv_bfloat16* Tl = (z == 0) ? g_wqtlo : (z == 1) ? g_wktlo : (z == 2) ? g_wvtlo : g_wotlo;
    const int x0 = blockIdx.x * 32, y0 = blockIdx.y * 32;
    const int tx = threadIdx.x, ty = threadIdx.y;
#pragma unroll
    for (int j = 0; j < 4; j++)
        t[ty + 8 * j][tx] = W[(size_t)(y0 + ty + 8 * j) * 1024 + x0 + tx];
    __syncthreads();
#pragma unroll
    for (int j = 0; j < 4; j++) {
        float v = t[tx][ty + 8 * j];
        __nv_bfloat16 h = __float2bfloat16(v);
        size_t idx = (size_t)(x0 + ty + 8 * j) * 1024 + y0 + tx;
        Th[idx] = h;
        Tl[idx] = __float2bfloat16(v - __bfloat162float(h));
    }
}

// V [bh][l][d] fp32 -> V^T split [bh][d][l] bf16 hi/lo
__global__ void __launch_bounds__(256) transpose_v()
{
    __shared__ float t[64][65];
    const int l0 = blockIdx.x * 64;
    const int bh = blockIdx.z;
    const int tid = threadIdx.x;
    const int r = tid >> 4, c4 = (tid & 15) * 4;
    const float* src = g_v + (size_t)bh * NL * NHD + (size_t)l0 * NHD;
#pragma unroll
    for (int tt = 0; tt < 4; tt++) {
        int row = r + tt * 16;
        float4 v = *(const float4*)(src + (size_t)row * NHD + c4);
        t[c4 + 0][row] = v.x;
        t[c4 + 1][row] = v.y;
        t[c4 + 2][row] = v.z;
        t[c4 + 3][row] = v.w;
    }
    __syncthreads();
    __nv_bfloat16* dh = g_vthi + (size_t)bh * NHD * NL + l0;
    __nv_bfloat16* dl = g_vtlo + (size_t)bh * NHD * NL + l0;
#pragma unroll
    for (int tt = 0; tt < 4; tt++) {
        int d = r + tt * 16;
#pragma unroll
        for (int k = 0; k < 4; k++) {
            float v = t[d][c4 + k];
            __nv_bfloat16 h = __float2bfloat16(v);
            dh[(size_t)d * NL + c4 + k] = h;
            dl[(size_t)d * NL + c4 + k] = __float2bfloat16(v - __bfloat162float(h));
        }
    }
}

// ---------------------------------------------------------------------------
// GEMM kernels
// ---------------------------------------------------------------------------
__global__ void __launch_bounds__(256) tc_gemm_qkv()
{
    const int n0 = blockIdx.x * 64;
    const int m0 = blockIdx.y * 128;
    const int z  = blockIdx.z;
    const __nv_bfloat16* Bh = (z == 0) ? g_wqthi : (z == 1) ? g_wkthi : g_wvthi;
    const __nv_bfloat16* Bl = (z == 0) ? g_wqtlo : (z == 1) ? g_wktlo : g_wvtlo;
    GEMM_ASYNC(g_xhi, g_xlo, Bh, Bl, NDIN, NDIN, NDIN / BK, m0, n0)

    const int mb = m0 + wm + (lane >> 2);
    const int cb = n0 + wn + (lane & 3) * 2;
#define EPQ(C, MO, CO) do {                                                        \
    int m = mb + (MO), col = cb + (CO);                                            \
    size_t idx = QKV_IDX(m, col);                                                  \
    if (z == 0)      { SPL(g_qhi, g_qlo, idx, (C).x, (C).y); }                     \
    else if (z == 1) { SPL(g_khi, g_klo, idx, (C).x, (C).y); }                     \
    else             { *(float2*)(g_v + idx) = make_float2((C).x, (C).y); }        \
    idx = QKV_IDX(m + 8, col);                                                     \
    if (z == 0)      { SPL(g_qhi, g_qlo, idx, (C).z, (C).w); }                     \
    else if (z == 1) { SPL(g_khi, g_klo, idx, (C).z, (C).w); }                     \
    else             { *(float2*)(g_v + idx) = make_float2((C).z, (C).w); }        \
} while (0)
    EPQ(c00, 0, 0);  EPQ(c01, 0, 8);  EPQ(c02, 0, 16);  EPQ(c03, 0, 24);
    EPQ(c10, 16, 0); EPQ(c11, 16, 8); EPQ(c12, 16, 16); EPQ(c13, 16, 24);
#undef EPQ
}

__global__ void __launch_bounds__(256) tc_gemm_qr()
{
    const int n0 = blockIdx.x * 64;
    const int m0 = blockIdx.y * 128;
    if (m0 + n0 < 1857) return;              // tile never read by gemm_s bias
    const int bh = blockIdx.z;
    const __nv_bfloat16* Ah = g_qhi + (size_t)bh * NL * NHD;
    const __nv_bfloat16* Al = g_qlo + (size_t)bh * NL * NHD;
    GEMM_ASYNC(Ah, Al, g_relhi, g_rello, NHD, NHD, NHD / BK, m0, n0)

    float* dst = g_qr + (size_t)bh * NL * NL;
    const int mb = m0 + wm + (lane >> 2);
    const int cb = n0 + wn + (lane & 3) * 2;
#define EPR(C, MO, CO) do {                                                        \
    int m = mb + (MO), col = cb + (CO);                                            \
    *(float2*)(dst + (size_t)m * NL + col)       = make_float2((C).x, (C).y);      \
    *(float2*)(dst + (size_t)(m + 8) * NL + col) = make_float2((C).z, (C).w);      \
} while (0)
    EPR(c00, 0, 0);  EPR(c01, 0, 8);  EPR(c02, 0, 16);  EPR(c03, 0, 24);
    EPR(c10, 16, 0); EPR(c11, 16, 8); EPR(c12, 16, 16); EPR(c13, 16, 24);
#undef EPR
}

// S = Q K^T + bias, scaled; band tiles only; fp32 out (masked region = junk)
__global__ void __launch_bounds__(256) tc_gemm_s()
{
    const int n0 = blockIdx.x * 64;          // key tile
    const int m0 = blockIdx.y * 128;         // query tile
    if (n0 >= m0 + 128) return;              // fully masked
    const int bh = blockIdx.z;
    const __nv_bfloat16* Ah = g_qhi + (size_t)bh * NL * NHD;
    const __nv_bfloat16* Al = g_qlo + (size_t)bh * NL * NHD;
    const __nv_bfloat16* Bh = g_khi + (size_t)bh * NL * NHD;
    const __nv_bfloat16* Bl = g_klo + (size_t)bh * NL * NHD;
    GEMM_ASYNC(Ah, Al, Bh, Bl, NHD, NHD, NHD / BK, m0, n0)

    float* sbase = g_s + (size_t)bh * NL * NL;
    const float* qrb = g_qr + (size_t)bh * NL * NL;
    const int mb = m0 + wm + (lane >> 2);
    const int cb = n0 + wn + (lane & 3) * 2;
#define EPS(C, MO, CO) do {                                                        \
    int m = mb + (MO), j = cb + (CO);                                              \
    {                                                                              \
        int k = j - m + (NL - 1);                                                  \
        float b0 = qrb[(size_t)m * NL + (j     <= m ? k     : 0)];                 \
        float b1 = qrb[(size_t)m * NL + (j + 1 <= m ? k + 1 : 0)];                 \
        *(float2*)(sbase + (size_t)m * NL + j) =                                   \
            make_float2(((C).x + b0) * 0.125f, ((C).y + b1) * 0.125f);             \
    }                                                                              \
    {                                                                              \
        int m2 = m + 8;                                                            \
        int k = j - m2 + (NL - 1);                                                 \
        float b0 = qrb[(size_t)m2 * NL + (j     <= m2 ? k     : 0)];               \
        float b1 = qrb[(size_t)m2 * NL + (j + 1 <= m2 ? k + 1 : 0)];               \
        *(float2*)(sbase + (size_t)m2 * NL + j) =                                  \
            make_float2(((C).z + b0) * 0.125f, ((C).w + b1) * 0.125f);             \
    }                                                                              \
} while (0)
    EPS(c00, 0, 0);  EPS(c01, 0, 8);  EPS(c02, 0, 16);  EPS(c03, 0, 24);
    EPS(c10, 16, 0); EPS(c11, 16, 8); EPS(c12, 16, 16); EPS(c13, 16, 24);
#undef EPS
}

// Row softmax: one block per (row, bh). Writes normalized P split,
// zero-padded to the enclosing 128-query tile's key bound.
__global__ void __launch_bounds__(256) softmax_rows()
{
    __shared__ float es[NL];
    __shared__ float red[8];
    const int i = blockIdx.x, bh = blockIdx.y;
    const int tid = threadIdx.x, lane = tid & 31, wid = tid >> 5;
    const float* srow = g_s + ((size_t)bh * NL + i) * NL;
    const int n  = i + 1;
    const int nw = ((i >> 7) + 1) << 7;      // round up to 128 (<= NL)

    float mx = -1e30f;
    for (int j = tid; j < n; j += 256) { float v = srow[j]; es[j] = v; mx = fmaxf(mx, v); }
#pragma unroll
    for (int s = 16; s >= 1; s >>= 1) mx = fmaxf(mx, __shfl_xor_sync(0xffffffffu, mx, s));
    if (lane == 0) red[wid] = mx;
    __syncthreads();
    if (tid == 0) {
        float m2 = red[0];
#pragma unroll
        for (int w = 1; w < 8; w++) m2 = fmaxf(m2, red[w]);
        red[0] = m2;
    }
    __syncthreads();
    mx = red[0];
    __syncthreads();

    float sum = 0.f;
    for (int j = tid; j < n; j += 256) { float p = __expf(es[j] - mx); es[j] = p; sum += p; }
#pragma unroll
    for (int s = 16; s >= 1; s >>= 1) sum += __shfl_xor_sync(0xffffffffu, sum, s);
    if (lane == 0) red[wid] = sum;
    __syncthreads();
    if (tid == 0) {
        float s2 = 0.f;
#pragma unroll
        for (int w = 0; w < 8; w++) s2 += red[w];
        red[0] = s2;
    }
    __syncthreads();
    const float inv = 1.0f / red[0];

    __nv_bfloat16* ph = g_phi + ((size_t)bh * NL + i) * NL;
    __nv_bfloat16* pl = g_plo + ((size_t)bh * NL + i) * NL;
    for (int j = tid; j < n; j += 256) {
        float p = es[j] * inv;
        __nv_bfloat16 h = __float2bfloat16(p);
        ph[j] = h;
        pl[j] = __float2bfloat16(p - __bfloat162float(h));
    }
    const __nv_bfloat16 z16 = __float2bfloat16(0.f);
    for (int j = n + tid; j < nw; j += 256) { ph[j] = z16; pl[j] = z16; }
}

// O = P V  (band k-range), writes ctx splits directly
__global__ void __launch_bounds__(256) tc_gemm_pv()
{
    const int m0 = blockIdx.y * 128;         // query tile
    const int bh = blockIdx.z;
    const __nv_bfloat16* Ah = g_phi + (size_t)bh * NL * NL;
    const __nv_bfloat16* Al = g_plo + (size_t)bh * NL * NL;
    const __nv_bfloat16* Bh = g_vthi + (size_t)bh * NHD * NL;
    const __nv_bfloat16* Bl = g_vtlo + (size_t)bh * NHD * NL;
    GEMM_ASYNC(Ah, Al, Bh, Bl, NL, NL, m0 / BK + 4, m0, 0)

    const int b = bh >> 4, h = bh & 15;
    const int mb = m0 + wm + (lane >> 2);
    const int cb = wn + (lane & 3) * 2;      // d
#define EPP(C, MO, CO) do {                                                        \
    int m = mb + (MO), d = cb + (CO);                                              \
    size_t idx = ((size_t)b * NL + m) * NDOUT + h * NHD + d;                       \
    SPL(g_ctxhi, g_ctxlo, idx, (C).x, (C).y);                                      \
    idx = ((size_t)b * NL + (m + 8)) * NDOUT + h * NHD + d;                        \
    SPL(g_ctxhi, g_ctxlo, idx, (C).z, (C).w);                                      \
} while (0)
    EPP(c00, 0, 0);  EPP(c01, 0, 8);  EPP(c02, 0, 16);  EPP(c03, 0, 24);
    EPP(c10, 16, 0); EPP(c11, 16, 8); EPP(c12, 16, 16); EPP(c13, 16, 24);
#undef EPP
}

__global__ void __launch_bounds__(256) tc_gemm_out(
    const float* __restrict__ bo, float* __restrict__ out)
{
    const int n0 = blockIdx.x * 64;
    const int m0 = blockIdx.y * 128;
    GEMM_ASYNC(g_ctxhi, g_ctxlo, g_wothi, g_wotlo, NDOUT, NDOUT, NDOUT / BK, m0, n0)

    const int mb = m0 + wm + (lane >> 2);
    const int cb = n0 + wn + (lane & 3) * 2;
#define EPO(C, MO, CO) do {                                                        \
    int m = mb + (MO), col = cb + (CO);                                            \
    float b0 = bo[col], b1 = bo[col + 1];                                          \
    *(float2*)(out + (size_t)m * NDOUT + col) =                                    \
        make_float2((C).x + b0, (C).y + b1);                                       \
    *(float2*)(out + (size_t)(m + 8) * NDOUT + col) =                              \
        make_float2((C).z + b0, (C).w + b1);                                       \
} while (0)
    EPO(c00, 0, 0);  EPO(c01, 0, 8);  EPO(c02, 0, 16);  EPO(c03, 0, 24);
    EPO(c10, 16, 0); EPO(c11, 16, 8); EPO(c12, 16, 16); EPO(c13, 16, 24);
#undef EPO
}

// ---------------------------------------------------------------------------

extern "C" void kernel_launch(void* const* d_in, const int* in_sizes, int n_in,
                              void* d_out, int out_size)
{
    const float* x   = (const float*)d_in[0];
    const float* Wq  = (const float*)d_in[1];
    const float* Wk  = (const float*)d_in[2];
    const float* Wv  = (const float*)d_in[3];
    const float* Wo  = (const float*)d_in[4];
    const float* bo  = (const float*)d_in[5];
    const float* rel = (const float*)d_in[6];
    float* out = (float*)d_out;

    cudaFuncSetAttribute(tc_gemm_qkv, cudaFuncAttributeMaxDynamicSharedMemorySize, SM_DYN);
    cudaFuncSetAttribute(tc_gemm_qr,  cudaFuncAttributeMaxDynamicSharedMemorySize, SM_DYN);
    cudaFuncSetAttribute(tc_gemm_s,   cudaFuncAttributeMaxDynamicSharedMemorySize, SM_DYN);
    cudaFuncSetAttribute(tc_gemm_pv,  cudaFuncAttributeMaxDynamicSharedMemorySize, SM_DYN);
    cudaFuncSetAttribute(tc_gemm_out, cudaFuncAttributeMaxDynamicSharedMemorySize, SM_DYN);

    prep_split_x  <<<NB * NL * NDIN / 1024, 256>>>(x);
    prep_split_rel<<<NL * NHD / 1024, 256>>>(rel);
    prep_wt<<<dim3(32, 32, 4), dim3(32, 8)>>>(Wq, Wk, Wv, Wo);

    tc_gemm_qkv<<<dim3(NDOUT / 64, NB * NL / 128, 3), 256, SM_DYN>>>();
    transpose_v<<<dim3(NL / 64, 1, NBH), 256>>>();
    tc_gemm_qr <<<dim3(NL / 64, NL / 128, NBH), 256, SM_DYN>>>();
    tc_gemm_s  <<<dim3(NL / 64, NL / 128, NBH), 256, SM_DYN>>>();
    softmax_rows<<<dim3(NL, NBH), 256>>>();
    tc_gemm_pv <<<dim3(1, NL / 128, NBH), 256, SM_DYN>>>();
    tc_gemm_out<<<dim3(NDOUT / 64, NB * NL / 128), 256, SM_DYN>>>(bo, out);
}